// round 2
// baseline (speedup 1.0000x reference)
#include <cuda_runtime.h>
#include <math.h>

#define NN   50000
#define DEG  16
#define IND  128
#define EDIM 64
#define ODIM 128

typedef unsigned long long u64;

// ---- scratch (device globals: allocation-free rule) ----
__device__ float g_A[NN * IND];            // h @ W1 (src-side pretrans)
__device__ float g_B[NN * IND];            // h @ W2 (dst-side pretrans)
__device__ float g_agg[NN * 4 * IND];      // [mean | max | min | std] per node
__device__ float g_Wsum[4 * IND * ODIM];   // Wp1+Wp2+Wp3 folded (scalers == 1)

// ---- f32x2 helpers (FFMA2 path: rt=1/SMSP vs rt=2 for FFMA-3reg) ----
__device__ __forceinline__ void fma2(u64 &d, u64 a, u64 b) {
    asm("fma.rn.f32x2 %0, %1, %2, %0;" : "+l"(d) : "l"(a), "l"(b));
}
__device__ __forceinline__ u64 dup2f(float x) {
    u64 r; asm("mov.b64 %0, {%1, %2};" : "=l"(r) : "f"(x), "f"(x)); return r;
}
__device__ __forceinline__ float2 unpack2(u64 v) {
    float2 r; asm("mov.b64 {%0, %1}, %2;" : "=f"(r.x), "=f"(r.y) : "l"(v)); return r;
}

// ============================================================
// K0: fold the three scaler blocks of W_post (amp = att = 1 since deg == 16)
// ============================================================
__global__ void k_wsum(const float* __restrict__ Wpost) {
    int i = blockIdx.x * blockDim.x + threadIdx.x;
    if (i < 4 * IND * ODIM) {
        int r = i >> 7, c = i & 127;
        g_Wsum[i] = Wpost[(IND + r) * ODIM + c]
                  + Wpost[(5 * IND + r) * ODIM + c]
                  + Wpost[(9 * IND + r) * ODIM + c];
    }
}

// ============================================================
// K1: [A|B] = h @ [W1 , W2]   (M=50000, K=128, N=256)
// 64-row tile, 256 threads, thread = 8 cols x 8 rows, f32x2 accum.
// h tile staged in shared pre-duplicated as f32x2 (kills per-FMA packs).
// ============================================================
__global__ __launch_bounds__(256) void k_ab(const float* __restrict__ h,
                                            const float* __restrict__ Wpre) {
    extern __shared__ u64 hs[];              // [64][130] padded
    const int m0 = blockIdx.x * 64;
    const int tid = threadIdx.x;

    for (int i = tid; i < 64 * 32; i += 256) {
        int m = i >> 5, k4 = i & 31;
        float4 v = make_float4(0.f, 0.f, 0.f, 0.f);
        if (m0 + m < NN) v = ((const float4*)(h + (size_t)(m0 + m) * IND))[k4];
        u64* d = hs + m * 130 + k4 * 4;
        d[0] = dup2f(v.x); d[1] = dup2f(v.y); d[2] = dup2f(v.z); d[3] = dup2f(v.w);
    }
    __syncthreads();

    const int tc = tid & 31, tr = tid >> 5;
    const int c0 = tc * 8, r0 = tr * 8;
    // virtual [W1|W2]: cols <128 from Wpre rows 0..127, cols >=128 from rows 128..255
    const float* wp = (c0 < IND) ? (Wpre + c0) : (Wpre + IND * IND + (c0 - IND));

    u64 acc[8][4];
    #pragma unroll
    for (int i = 0; i < 8; i++)
        #pragma unroll
        for (int j = 0; j < 4; j++) acc[i][j] = 0ull;

    #pragma unroll 2
    for (int k = 0; k < IND; k++) {
        ulonglong2 wq0 = *(const ulonglong2*)(wp + (size_t)k * IND);
        ulonglong2 wq1 = *(const ulonglong2*)(wp + (size_t)k * IND + 4);
        #pragma unroll
        for (int i = 0; i < 8; i++) {
            u64 av = hs[(r0 + i) * 130 + k];      // broadcast LDS.64 (pre-dup'd)
            fma2(acc[i][0], av, wq0.x);
            fma2(acc[i][1], av, wq0.y);
            fma2(acc[i][2], av, wq1.x);
            fma2(acc[i][3], av, wq1.y);
        }
    }

    const bool isA = (c0 < IND);
    const int cb = isA ? c0 : (c0 - IND);
    float* outb = isA ? g_A : g_B;
    #pragma unroll
    for (int i = 0; i < 8; i++) {
        int m = m0 + r0 + i;
        if (m < NN) {
            float* o = outb + (size_t)m * IND + cb;
            #pragma unroll
            for (int jj = 0; jj < 4; jj++) {
                float2 u = unpack2(acc[i][jj]);
                *(float2*)(o + 2 * jj) = u;
            }
        }
    }
}

// ============================================================
// K2: per-node edge matvec + 4-aggregator reduce.
// 1 warp per node, 8 nodes/block. Lane owns col pairs (2L,2L+1) and (64+2L,65+2L).
// e_j = A[src_j] + B[n] + b_pre + ef_j @ W3, reduced over j=0..15 in registers.
// W3 (32KB) in shared; node's ef (16x64) staged duplicated as f32x2.
// ============================================================
__global__ __launch_bounds__(256, 2) void k_edge(const float* __restrict__ ef,
                                                 const int* __restrict__ src,
                                                 const float* __restrict__ Wpre,
                                                 const float* __restrict__ bpre) {
    extern __shared__ char smem2[];
    float* W3s = (float*)smem2;                                   // [64][128] = 32KB
    u64*   ef2 = (u64*)(smem2 + EDIM * IND * sizeof(float));      // [8][16][64] = 64KB

    const int tid  = threadIdx.x;
    const int warp = tid >> 5, lane = tid & 31;
    const int n    = blockIdx.x * 8 + warp;                       // grid = NN/8 exact

    // W3 = Wpre rows 256..319 (contiguous 64x128 block)
    for (int i = tid; i < EDIM * IND; i += 256) W3s[i] = Wpre[2 * IND * IND + i];

    const float* efp = ef + (size_t)n * (DEG * EDIM);
    u64* myef = ef2 + warp * (DEG * EDIM);
    for (int i = lane; i < DEG * EDIM; i += 32) myef[i] = dup2f(efp[i]);
    __syncthreads();

    u64 acc[DEG][2];
    #pragma unroll
    for (int j = 0; j < DEG; j++) { acc[j][0] = 0ull; acc[j][1] = 0ull; }

    // matvec: 16 edges x 64 k x 2 col-pairs, k chunked by 4 to hoist weight loads
    for (int kc = 0; kc < EDIM; kc += 4) {
        u64 w0[4], w1[4];
        #pragma unroll
        for (int q = 0; q < 4; q++) {
            w0[q] = *(const u64*)&W3s[(kc + q) * IND + 2 * lane];
            w1[q] = *(const u64*)&W3s[(kc + q) * IND + 64 + 2 * lane];
        }
        #pragma unroll
        for (int j = 0; j < DEG; j++) {
            const u64* ap = myef + j * EDIM + kc;
            ulonglong2 a01 = *(const ulonglong2*)(ap);
            ulonglong2 a23 = *(const ulonglong2*)(ap + 2);
            fma2(acc[j][0], a01.x, w0[0]); fma2(acc[j][1], a01.x, w1[0]);
            fma2(acc[j][0], a01.y, w0[1]); fma2(acc[j][1], a01.y, w1[1]);
            fma2(acc[j][0], a23.x, w0[2]); fma2(acc[j][1], a23.x, w1[2]);
            fma2(acc[j][0], a23.y, w0[3]); fma2(acc[j][1], a23.y, w1[3]);
        }
    }

    const int c0 = 2 * lane, c1 = 64 + 2 * lane;
    float2 B0 = *(const float2*)&g_B[(size_t)n * IND + c0];
    float2 B1 = *(const float2*)&g_B[(size_t)n * IND + c1];
    float2 bp0 = *(const float2*)&bpre[c0];
    float2 bp1 = *(const float2*)&bpre[c1];
    B0.x += bp0.x; B0.y += bp0.y; B1.x += bp1.x; B1.y += bp1.y;

    int sreg[DEG];
    const int* srcp = src + n * DEG;
    #pragma unroll
    for (int j = 0; j < DEG; j++) sreg[j] = srcp[j];

    float2 s1a = {0.f, 0.f}, s2a = {0.f, 0.f};
    float2 s1b = {0.f, 0.f}, s2b = {0.f, 0.f};
    float2 mxa = {-3.402823466e38f, -3.402823466e38f}, mna = {3.402823466e38f, 3.402823466e38f};
    float2 mxb = mxa, mnb = mna;

    #pragma unroll
    for (int j = 0; j < DEG; j++) {
        const float* Ar = g_A + (size_t)sreg[j] * IND;
        float2 a0 = *(const float2*)&Ar[c0];
        float2 a1 = *(const float2*)&Ar[c1];
        float2 e0 = unpack2(acc[j][0]);
        float2 e1 = unpack2(acc[j][1]);
        e0.x += a0.x + B0.x; e0.y += a0.y + B0.y;
        e1.x += a1.x + B1.x; e1.y += a1.y + B1.y;
        s1a.x += e0.x; s1a.y += e0.y; s1b.x += e1.x; s1b.y += e1.y;
        s2a.x += e0.x * e0.x; s2a.y += e0.y * e0.y;
        s2b.x += e1.x * e1.x; s2b.y += e1.y * e1.y;
        mxa.x = fmaxf(mxa.x, e0.x); mxa.y = fmaxf(mxa.y, e0.y);
        mxb.x = fmaxf(mxb.x, e1.x); mxb.y = fmaxf(mxb.y, e1.y);
        mna.x = fminf(mna.x, e0.x); mna.y = fminf(mna.y, e0.y);
        mnb.x = fminf(mnb.x, e1.x); mnb.y = fminf(mnb.y, e1.y);
    }

    const float inv = 1.0f / (float)DEG;
    float2 mea = {s1a.x * inv, s1a.y * inv};
    float2 meb = {s1b.x * inv, s1b.y * inv};
    float2 sda, sdb;
    sda.x = sqrtf(fmaxf(s2a.x * inv - mea.x * mea.x, 0.f) + 1e-5f);
    sda.y = sqrtf(fmaxf(s2a.y * inv - mea.y * mea.y, 0.f) + 1e-5f);
    sdb.x = sqrtf(fmaxf(s2b.x * inv - meb.x * meb.x, 0.f) + 1e-5f);
    sdb.y = sqrtf(fmaxf(s2b.y * inv - meb.y * meb.y, 0.f) + 1e-5f);

    float* aggp = g_agg + (size_t)n * (4 * IND);
    *(float2*)&aggp[c0]            = mea; *(float2*)&aggp[c1]            = meb;
    *(float2*)&aggp[IND + c0]      = mxa; *(float2*)&aggp[IND + c1]      = mxb;
    *(float2*)&aggp[2 * IND + c0]  = mna; *(float2*)&aggp[2 * IND + c1]  = mnb;
    *(float2*)&aggp[3 * IND + c0]  = sda; *(float2*)&aggp[3 * IND + c1]  = sdb;
}

// ============================================================
// K3: out = h @ Wp0 + agg @ Wsum + b_post   (M=50000, K=640, N=128)
// 64-row tile, K chunked by 128; input chunk staged duplicated as f32x2.
// ============================================================
__global__ __launch_bounds__(256) void k_post(const float* __restrict__ h,
                                              const float* __restrict__ Wpost,
                                              const float* __restrict__ bpost,
                                              float* __restrict__ out) {
    extern __shared__ u64 xs[];              // [64][130] padded
    const int m0 = blockIdx.x * 64;
    const int tid = threadIdx.x;
    const int tc = tid & 15, tr = tid >> 4;
    const int c0 = tc * 8, r0 = tr * 4;

    u64 acc[4][4];
    #pragma unroll
    for (int i = 0; i < 4; i++)
        #pragma unroll
        for (int j = 0; j < 4; j++) acc[i][j] = 0ull;

    for (int chunk = 0; chunk < 5; chunk++) {
        __syncthreads();
        for (int i = tid; i < 64 * 32; i += 256) {
            int m = i >> 5, k4 = i & 31;
            float4 v = make_float4(0.f, 0.f, 0.f, 0.f);
            int mm = m0 + m;
            if (mm < NN) {
                v = (chunk == 0)
                    ? ((const float4*)(h + (size_t)mm * IND))[k4]
                    : ((const float4*)(g_agg + (size_t)mm * 4 * IND + (chunk - 1) * IND))[k4];
            }
            u64* d = xs + m * 130 + k4 * 4;
            d[0] = dup2f(v.x); d[1] = dup2f(v.y); d[2] = dup2f(v.z); d[3] = dup2f(v.w);
        }
        __syncthreads();

        const float* wb = (chunk == 0) ? (Wpost + c0)
                                       : (g_Wsum + (size_t)(chunk - 1) * IND * ODIM + c0);
        #pragma unroll 2
        for (int k = 0; k < IND; k++) {
            ulonglong2 wq0 = *(const ulonglong2*)(wb + (size_t)k * ODIM);
            ulonglong2 wq1 = *(const ulonglong2*)(wb + (size_t)k * ODIM + 4);
            #pragma unroll
            for (int i = 0; i < 4; i++) {
                u64 av = xs[(r0 + i) * 130 + k];
                fma2(acc[i][0], av, wq0.x);
                fma2(acc[i][1], av, wq0.y);
                fma2(acc[i][2], av, wq1.x);
                fma2(acc[i][3], av, wq1.y);
            }
        }
    }

    float2 bp[4];
    #pragma unroll
    for (int jj = 0; jj < 4; jj++) bp[jj] = *(const float2*)&bpost[c0 + 2 * jj];

    #pragma unroll
    for (int i = 0; i < 4; i++) {
        int m = m0 + r0 + i;
        if (m < NN) {
            float* o = out + (size_t)m * ODIM + c0;
            #pragma unroll
            for (int jj = 0; jj < 4; jj++) {
                float2 u = unpack2(acc[i][jj]);
                u.x += bp[jj].x; u.y += bp[jj].y;
                *(float2*)(o + 2 * jj) = u;
            }
        }
    }
}

// ============================================================
extern "C" void kernel_launch(void* const* d_in, const int* in_sizes, int n_in,
                              void* d_out, int out_size) {
    const float* h     = (const float*)d_in[0];
    const float* ef    = (const float*)d_in[1];
    const int*   src   = (const int*)d_in[2];
    // d_in[3] = dst: implicit (dst[e] = e/16), unused
    const float* Wpre  = (const float*)d_in[4];
    const float* bpre  = (const float*)d_in[5];
    const float* Wpost = (const float*)d_in[6];
    const float* bpost = (const float*)d_in[7];
    float* out = (float*)d_out;

    const int smem_ab   = 64 * 130 * sizeof(u64);                         // 66560
    const int smem_edge = EDIM * IND * sizeof(float) + 8 * DEG * EDIM * 8; // 98304
    const int smem_post = 64 * 130 * sizeof(u64);                         // 66560

    static bool attr_done = false;
    if (!attr_done) {
        cudaFuncSetAttribute(k_ab,   cudaFuncAttributeMaxDynamicSharedMemorySize, smem_ab);
        cudaFuncSetAttribute(k_edge, cudaFuncAttributeMaxDynamicSharedMemorySize, smem_edge);
        cudaFuncSetAttribute(k_post, cudaFuncAttributeMaxDynamicSharedMemorySize, smem_post);
        attr_done = true;
    }

    k_wsum<<<(4 * IND * ODIM + 255) / 256, 256>>>(Wpost);
    k_ab  <<<(NN + 63) / 64, 256, smem_ab>>>(h, Wpre);
    k_edge<<<NN / 8, 256, smem_edge>>>(ef, src, Wpre, bpre);
    k_post<<<(NN + 63) / 64, 256, smem_post>>>(h, Wpost, bpost, out);
}

// round 3
// speedup vs baseline: 1.4838x; 1.4838x over previous
#include <cuda_runtime.h>
#include <math.h>

#define NN   50000
#define DEG  16
#define IND  128
#define EDIM 64
#define ODIM 128
#define MTILE 128
#define KC   16

typedef unsigned long long u64;

// ---- scratch (device globals: allocation-free rule) ----
__device__ float g_A[NN * IND];            // h @ W1 (src-side pretrans)
__device__ float g_B[NN * IND];            // h @ W2 (dst-side pretrans)
__device__ float g_agg[NN * 4 * IND];      // [mean | max | min | std] per node
__device__ float g_Wsum[4 * IND * ODIM];   // Wp1+Wp2+Wp3 folded (scalers == 1)

// ---- f32x2 helpers ----
__device__ __forceinline__ void fma2(u64 &d, u64 a, u64 b) {
    asm("fma.rn.f32x2 %0, %1, %2, %0;" : "+l"(d) : "l"(a), "l"(b));
}
__device__ __forceinline__ u64 dup2f(float x) {
    u64 r; asm("mov.b64 %0, {%1, %2};" : "=l"(r) : "f"(x), "f"(x)); return r;
}
__device__ __forceinline__ float2 unpack2(u64 v) {
    float2 r; asm("mov.b64 {%0, %1}, %2;" : "=f"(r.x), "=f"(r.y) : "l"(v)); return r;
}

// ============================================================
// K0: fold scaler blocks of W_post (amp = att = 1 since deg == 16)
// ============================================================
__global__ void k_wsum(const float* __restrict__ Wpost) {
    int i = blockIdx.x * blockDim.x + threadIdx.x;
    if (i < 4 * IND * ODIM) {
        int r = i >> 7, c = i & 127;
        g_Wsum[i] = Wpost[(IND + r) * ODIM + c]
                  + Wpost[(5 * IND + r) * ODIM + c]
                  + Wpost[(9 * IND + r) * ODIM + c];
    }
}

// ============================================================
// K1: A/B = h @ W1 / h @ W2.  grid (391, 2): y = which half.
// Double-buffered smem GEMM: 128x128 tile, K=128 in chunks of 16.
// Inner loop: pure LDS + FFMA2 (conflict-free W reads via g*32+tc*2 cols).
// ============================================================
__global__ __launch_bounds__(256, 2) void k_ab(const float* __restrict__ h,
                                               const float* __restrict__ Wpre) {
    extern __shared__ char sm[];
    u64*   Xs = (u64*)sm;                         // [2][128][16] dup'd  = 32KB
    float* Ws = (float*)(sm + 2 * MTILE * KC * 8); // [2][16][128]        = 16KB

    const int m0  = blockIdx.x * MTILE;
    const float* Wsrc = Wpre + (size_t)blockIdx.y * IND * IND;
    float* outb = blockIdx.y ? g_B : g_A;

    const int tid = threadIdx.x;
    const int tc = tid & 15, tr = tid >> 4;
    const int r0 = tr * 8;

    u64 acc[8][4];
    #pragma unroll
    for (int i = 0; i < 8; i++)
        #pragma unroll
        for (int g = 0; g < 4; g++) acc[i][g] = 0ull;

    float4 px[2], pw[2];
    const int NCH = IND / KC;   // 8

    // prefetch chunk 0
    #pragma unroll
    for (int t = 0; t < 2; t++) {
        int it = tid + t * 256;
        int row = it >> 2, q = it & 3;
        int m = m0 + row;
        px[t] = make_float4(0.f, 0.f, 0.f, 0.f);
        if (m < NN) px[t] = *(const float4*)(h + (size_t)m * IND + q * 4);
        int k = it >> 5, c4 = it & 31;
        pw[t] = *(const float4*)(Wsrc + (size_t)k * IND + c4 * 4);
    }
    // stage chunk 0
    #pragma unroll
    for (int t = 0; t < 2; t++) {
        int it = tid + t * 256;
        int row = it >> 2, q = it & 3;
        ulonglong2 d0 = {dup2f(px[t].x), dup2f(px[t].y)};
        ulonglong2 d1 = {dup2f(px[t].z), dup2f(px[t].w)};
        *(ulonglong2*)&Xs[row * KC + q * 4]     = d0;
        *(ulonglong2*)&Xs[row * KC + q * 4 + 2] = d1;
        int k = it >> 5, c4 = it & 31;
        *(float4*)&Ws[k * IND + c4 * 4] = pw[t];
    }
    __syncthreads();

    for (int c = 0; c < NCH; c++) {
        if (c + 1 < NCH) {
            #pragma unroll
            for (int t = 0; t < 2; t++) {
                int it = tid + t * 256;
                int row = it >> 2, q = it & 3;
                int m = m0 + row;
                px[t] = make_float4(0.f, 0.f, 0.f, 0.f);
                if (m < NN) px[t] = *(const float4*)(h + (size_t)m * IND + (c + 1) * KC + q * 4);
                int k = it >> 5, c4 = it & 31;
                pw[t] = *(const float4*)(Wsrc + (size_t)((c + 1) * KC + k) * IND + c4 * 4);
            }
        }
        const u64*   Xb = Xs + (c & 1) * MTILE * KC;
        const float* Wb = Ws + (c & 1) * KC * IND;
        #pragma unroll
        for (int kk = 0; kk < KC; kk += 2) {
            u64 w0[4], w1[4];
            #pragma unroll
            for (int g = 0; g < 4; g++) {
                w0[g] = *(const u64*)&Wb[kk * IND + g * 32 + tc * 2];
                w1[g] = *(const u64*)&Wb[(kk + 1) * IND + g * 32 + tc * 2];
            }
            #pragma unroll
            for (int i = 0; i < 8; i++) {
                ulonglong2 xv = *(const ulonglong2*)&Xb[(r0 + i) * KC + kk];
                #pragma unroll
                for (int g = 0; g < 4; g++) {
                    fma2(acc[i][g], xv.x, w0[g]);
                    fma2(acc[i][g], xv.y, w1[g]);
                }
            }
        }
        if (c + 1 < NCH) {
            u64*   Xn = Xs + ((c + 1) & 1) * MTILE * KC;
            float* Wn = Ws + ((c + 1) & 1) * KC * IND;
            #pragma unroll
            for (int t = 0; t < 2; t++) {
                int it = tid + t * 256;
                int row = it >> 2, q = it & 3;
                ulonglong2 d0 = {dup2f(px[t].x), dup2f(px[t].y)};
                ulonglong2 d1 = {dup2f(px[t].z), dup2f(px[t].w)};
                *(ulonglong2*)&Xn[row * KC + q * 4]     = d0;
                *(ulonglong2*)&Xn[row * KC + q * 4 + 2] = d1;
                int k = it >> 5, c4 = it & 31;
                *(float4*)&Wn[k * IND + c4 * 4] = pw[t];
            }
        }
        __syncthreads();
    }

    #pragma unroll
    for (int i = 0; i < 8; i++) {
        int m = m0 + r0 + i;
        if (m < NN) {
            float* o = outb + (size_t)m * IND;
            #pragma unroll
            for (int g = 0; g < 4; g++) {
                float2 u = unpack2(acc[i][g]);
                *(float2*)(o + g * 32 + tc * 2) = u;
            }
        }
    }
}

// ============================================================
// K2: per-node edge matvec + 4-aggregator reduce (1 warp/node, 8 nodes/block).
// e_j = A[src_j] + B[n] + b_pre + ef_j @ W3; reduce over 16 edges in regs.
// All-smem inner loop; src/B/bias hoisted before matvec for latency overlap.
// ============================================================
__global__ __launch_bounds__(256, 2) void k_edge(const float* __restrict__ ef,
                                                 const int* __restrict__ src,
                                                 const float* __restrict__ Wpre,
                                                 const float* __restrict__ bpre) {
    extern __shared__ char smem2[];
    float* W3s = (float*)smem2;                                   // [64][128] = 32KB
    u64*   ef2 = (u64*)(smem2 + EDIM * IND * sizeof(float));      // [8][16][64] dup = 64KB

    const int tid  = threadIdx.x;
    const int warp = tid >> 5, lane = tid & 31;
    const int n    = blockIdx.x * 8 + warp;

    // W3 = Wpre rows 256..319, staged via float4
    for (int i = tid; i < EDIM * IND / 4; i += 256)
        ((float4*)W3s)[i] = ((const float4*)(Wpre + 2 * IND * IND))[i];

    // hoisted scalar state (overlaps staging latency)
    const int c0 = 2 * lane, c1 = 64 + 2 * lane;
    int sreg[DEG];
    const int* srcp = src + n * DEG;
    #pragma unroll
    for (int j = 0; j < DEG; j++) sreg[j] = srcp[j];

    float2 B0 = *(const float2*)&g_B[(size_t)n * IND + c0];
    float2 B1 = *(const float2*)&g_B[(size_t)n * IND + c1];
    float2 bp0 = *(const float2*)&bpre[c0];
    float2 bp1 = *(const float2*)&bpre[c1];
    B0.x += bp0.x; B0.y += bp0.y; B1.x += bp1.x; B1.y += bp1.y;

    // ef tile staged duplicated as f32x2 (float4 global reads)
    const float* efp = ef + (size_t)n * (DEG * EDIM);
    u64* myef = ef2 + warp * (DEG * EDIM);
    for (int i = lane; i < DEG * EDIM / 4; i += 32) {
        float4 v = ((const float4*)efp)[i];
        u64* d = myef + i * 4;
        d[0] = dup2f(v.x); d[1] = dup2f(v.y); d[2] = dup2f(v.z); d[3] = dup2f(v.w);
    }
    __syncthreads();

    u64 acc[DEG][2];
    #pragma unroll
    for (int j = 0; j < DEG; j++) { acc[j][0] = 0ull; acc[j][1] = 0ull; }

    for (int kc = 0; kc < EDIM; kc += 4) {
        u64 w0[4], w1[4];
        #pragma unroll
        for (int q = 0; q < 4; q++) {
            w0[q] = *(const u64*)&W3s[(kc + q) * IND + c0];
            w1[q] = *(const u64*)&W3s[(kc + q) * IND + c1];
        }
        #pragma unroll
        for (int j = 0; j < DEG; j++) {
            const u64* ap = myef + j * EDIM + kc;
            ulonglong2 a01 = *(const ulonglong2*)(ap);
            ulonglong2 a23 = *(const ulonglong2*)(ap + 2);
            fma2(acc[j][0], a01.x, w0[0]); fma2(acc[j][1], a01.x, w1[0]);
            fma2(acc[j][0], a01.y, w0[1]); fma2(acc[j][1], a01.y, w1[1]);
            fma2(acc[j][0], a23.x, w0[2]); fma2(acc[j][1], a23.x, w1[2]);
            fma2(acc[j][0], a23.y, w0[3]); fma2(acc[j][1], a23.y, w1[3]);
        }
    }

    float2 s1a = {0.f, 0.f}, s2a = {0.f, 0.f};
    float2 s1b = {0.f, 0.f}, s2b = {0.f, 0.f};
    float2 mxa = {-3.402823466e38f, -3.402823466e38f}, mna = {3.402823466e38f, 3.402823466e38f};
    float2 mxb = mxa, mnb = mna;

    #pragma unroll
    for (int j = 0; j < DEG; j++) {
        const float* Ar = g_A + (size_t)sreg[j] * IND;
        float2 a0 = *(const float2*)&Ar[c0];
        float2 a1 = *(const float2*)&Ar[c1];
        float2 e0 = unpack2(acc[j][0]);
        float2 e1 = unpack2(acc[j][1]);
        e0.x += a0.x + B0.x; e0.y += a0.y + B0.y;
        e1.x += a1.x + B1.x; e1.y += a1.y + B1.y;
        s1a.x += e0.x; s1a.y += e0.y; s1b.x += e1.x; s1b.y += e1.y;
        s2a.x += e0.x * e0.x; s2a.y += e0.y * e0.y;
        s2b.x += e1.x * e1.x; s2b.y += e1.y * e1.y;
        mxa.x = fmaxf(mxa.x, e0.x); mxa.y = fmaxf(mxa.y, e0.y);
        mxb.x = fmaxf(mxb.x, e1.x); mxb.y = fmaxf(mxb.y, e1.y);
        mna.x = fminf(mna.x, e0.x); mna.y = fminf(mna.y, e0.y);
        mnb.x = fminf(mnb.x, e1.x); mnb.y = fminf(mnb.y, e1.y);
    }

    const float inv = 1.0f / (float)DEG;
    float2 mea = {s1a.x * inv, s1a.y * inv};
    float2 meb = {s1b.x * inv, s1b.y * inv};
    float2 sda, sdb;
    sda.x = sqrtf(fmaxf(s2a.x * inv - mea.x * mea.x, 0.f) + 1e-5f);
    sda.y = sqrtf(fmaxf(s2a.y * inv - mea.y * mea.y, 0.f) + 1e-5f);
    sdb.x = sqrtf(fmaxf(s2b.x * inv - meb.x * meb.x, 0.f) + 1e-5f);
    sdb.y = sqrtf(fmaxf(s2b.y * inv - meb.y * meb.y, 0.f) + 1e-5f);

    float* aggp = g_agg + (size_t)n * (4 * IND);
    *(float2*)&aggp[c0]            = mea; *(float2*)&aggp[c1]            = meb;
    *(float2*)&aggp[IND + c0]      = mxa; *(float2*)&aggp[IND + c1]      = mxb;
    *(float2*)&aggp[2 * IND + c0]  = mna; *(float2*)&aggp[2 * IND + c1]  = mnb;
    *(float2*)&aggp[3 * IND + c0]  = sda; *(float2*)&aggp[3 * IND + c1]  = sdb;
}

// ============================================================
// K3: out = [h | agg] @ [Wp0 ; Wsum] + b_post.  K=640 in 40 chunks of 16.
// Same double-buffered smem GEMM as k_ab.
// ============================================================
__global__ __launch_bounds__(256, 2) void k_post(const float* __restrict__ h,
                                                 const float* __restrict__ Wpost,
                                                 const float* __restrict__ bpost,
                                                 float* __restrict__ out) {
    extern __shared__ char sm[];
    u64*   Xs = (u64*)sm;                          // [2][128][16]
    float* Ws = (float*)(sm + 2 * MTILE * KC * 8); // [2][16][128]

    const int m0  = blockIdx.x * MTILE;
    const int tid = threadIdx.x;
    const int tc = tid & 15, tr = tid >> 4;
    const int r0 = tr * 8;

    u64 acc[8][4];
    #pragma unroll
    for (int i = 0; i < 8; i++)
        #pragma unroll
        for (int g = 0; g < 4; g++) acc[i][g] = 0ull;

    float4 px[2], pw[2];
    const int NCH = 40;

    // prefetch chunk 0 (chunk<8 -> h / Wpost; else -> g_agg / g_Wsum)
    #pragma unroll
    for (int t = 0; t < 2; t++) {
        int it = tid + t * 256;
        int row = it >> 2, q = it & 3;
        int m = m0 + row;
        px[t] = make_float4(0.f, 0.f, 0.f, 0.f);
        if (m < NN) px[t] = *(const float4*)(h + (size_t)m * IND + q * 4);
        int k = it >> 5, c4 = it & 31;
        pw[t] = *(const float4*)(Wpost + (size_t)k * ODIM + c4 * 4);
    }
    #pragma unroll
    for (int t = 0; t < 2; t++) {
        int it = tid + t * 256;
        int row = it >> 2, q = it & 3;
        ulonglong2 d0 = {dup2f(px[t].x), dup2f(px[t].y)};
        ulonglong2 d1 = {dup2f(px[t].z), dup2f(px[t].w)};
        *(ulonglong2*)&Xs[row * KC + q * 4]     = d0;
        *(ulonglong2*)&Xs[row * KC + q * 4 + 2] = d1;
        int k = it >> 5, c4 = it & 31;
        *(float4*)&Ws[k * ODIM + c4 * 4] = pw[t];
    }
    __syncthreads();

    for (int c = 0; c < NCH; c++) {
        if (c + 1 < NCH) {
            int cn = c + 1;
            #pragma unroll
            for (int t = 0; t < 2; t++) {
                int it = tid + t * 256;
                int row = it >> 2, q = it & 3;
                int m = m0 + row;
                px[t] = make_float4(0.f, 0.f, 0.f, 0.f);
                if (m < NN) {
                    const float* p = (cn < 8)
                        ? (h + (size_t)m * IND + cn * KC + q * 4)
                        : (g_agg + (size_t)m * 4 * IND + (cn - 8) * KC + q * 4);
                    px[t] = *(const float4*)p;
                }
                int k = it >> 5, c4 = it & 31;
                const float* wp = (cn < 8)
                    ? (Wpost + (size_t)(cn * KC + k) * ODIM + c4 * 4)
                    : (g_Wsum + (size_t)((cn - 8) * KC + k) * ODIM + c4 * 4);
                pw[t] = *(const float4*)wp;
            }
        }
        const u64*   Xb = Xs + (c & 1) * MTILE * KC;
        const float* Wb = Ws + (c & 1) * KC * ODIM;
        #pragma unroll
        for (int kk = 0; kk < KC; kk += 2) {
            u64 w0[4], w1[4];
            #pragma unroll
            for (int g = 0; g < 4; g++) {
                w0[g] = *(const u64*)&Wb[kk * ODIM + g * 32 + tc * 2];
                w1[g] = *(const u64*)&Wb[(kk + 1) * ODIM + g * 32 + tc * 2];
            }
            #pragma unroll
            for (int i = 0; i < 8; i++) {
                ulonglong2 xv = *(const ulonglong2*)&Xb[(r0 + i) * KC + kk];
                #pragma unroll
                for (int g = 0; g < 4; g++) {
                    fma2(acc[i][g], xv.x, w0[g]);
                    fma2(acc[i][g], xv.y, w1[g]);
                }
            }
        }
        if (c + 1 < NCH) {
            u64*   Xn = Xs + ((c + 1) & 1) * MTILE * KC;
            float* Wn = Ws + ((c + 1) & 1) * KC * ODIM;
            #pragma unroll
            for (int t = 0; t < 2; t++) {
                int it = tid + t * 256;
                int row = it >> 2, q = it & 3;
                ulonglong2 d0 = {dup2f(px[t].x), dup2f(px[t].y)};
                ulonglong2 d1 = {dup2f(px[t].z), dup2f(px[t].w)};
                *(ulonglong2*)&Xn[row * KC + q * 4]     = d0;
                *(ulonglong2*)&Xn[row * KC + q * 4 + 2] = d1;
                int k = it >> 5, c4 = it & 31;
                *(float4*)&Wn[k * ODIM + c4 * 4] = pw[t];
            }
        }
        __syncthreads();
    }

    #pragma unroll
    for (int i = 0; i < 8; i++) {
        int m = m0 + r0 + i;
        if (m < NN) {
            float* o = out + (size_t)m * ODIM;
            #pragma unroll
            for (int g = 0; g < 4; g++) {
                float2 b = *(const float2*)&bpost[g * 32 + tc * 2];
                float2 u = unpack2(acc[i][g]);
                u.x += b.x; u.y += b.y;
                *(float2*)(o + g * 32 + tc * 2) = u;
            }
        }
    }
}

// ============================================================
extern "C" void kernel_launch(void* const* d_in, const int* in_sizes, int n_in,
                              void* d_out, int out_size) {
    const float* h     = (const float*)d_in[0];
    const float* ef    = (const float*)d_in[1];
    const int*   src   = (const int*)d_in[2];
    // d_in[3] = dst: implicit (dst[e] = e/16), unused
    const float* Wpre  = (const float*)d_in[4];
    const float* bpre  = (const float*)d_in[5];
    const float* Wpost = (const float*)d_in[6];
    const float* bpost = (const float*)d_in[7];
    float* out = (float*)d_out;

    const int smem_gemm = 2 * MTILE * KC * 8 + 2 * KC * 128 * 4;           // 49152
    const int smem_edge = EDIM * IND * sizeof(float) + 8 * DEG * EDIM * 8; // 98304

    static bool attr_done = false;
    if (!attr_done) {
        cudaFuncSetAttribute(k_ab,   cudaFuncAttributeMaxDynamicSharedMemorySize, smem_gemm);
        cudaFuncSetAttribute(k_edge, cudaFuncAttributeMaxDynamicSharedMemorySize, smem_edge);
        cudaFuncSetAttribute(k_post, cudaFuncAttributeMaxDynamicSharedMemorySize, smem_gemm);
        attr_done = true;
    }

    const int mblocks = (NN + MTILE - 1) / MTILE;   // 391
    k_wsum<<<(4 * IND * ODIM + 255) / 256, 256>>>(Wpost);
    dim3 gab(mblocks, 2);
    k_ab  <<<gab, 256, smem_gemm>>>(h, Wpre);
    k_edge<<<NN / 8, 256, smem_edge>>>(ef, src, Wpre, bpre);
    k_post<<<mblocks, 256, smem_gemm>>>(h, Wpost, bpost, out);
}